// round 11
// baseline (speedup 1.0000x reference)
#include <cuda_runtime.h>
#include <math.h>

// ---------------- problem constants ----------------
#define B_   2
#define T_   2048
#define E_   1024
#define H_   16
#define HD_  64
#define L_   4
#define V_   32000
#define F_   4096            // 4*E
#define BT_  (B_*T_)         // 4096
#define EPS_ 1e-5f

// ---------------- device scratch (statics: allocation-free at launch) ----------------
__device__ float g_x [BT_*E_];
__device__ float g_h [BT_*E_];
__device__ float g_q [BT_*E_];
__device__ float g_k [BT_*E_];
__device__ float g_v [BT_*E_];
__device__ float g_a [BT_*E_];
__device__ float g_ff[BT_*F_];
__device__ float g_wq[E_*E_];
__device__ float g_wk[E_*E_];
__device__ float g_wv[E_*E_];
__device__ float g_logits[(size_t)BT_ * V_];   // only used if out buffer lacks logits
__device__ float g_rowloss[BT_];
__device__ float g_loss_dummy[1];

// ---------------- embedding ----------------
__global__ void embed_k(const int* __restrict__ idx, const float* __restrict__ tok,
                        const float* __restrict__ pos, float* __restrict__ x) {
    int i = blockIdx.x * blockDim.x + threadIdx.x;
    if (i >= BT_ * E_) return;
    int e  = i & (E_ - 1);
    int bt = i >> 10;            // /E_
    int t  = bt & (T_ - 1);
    x[i] = tok[(size_t)idx[bt] * E_ + e] + pos[(size_t)t * E_ + e];
}

// ---------------- layernorm (one block per row) ----------------
__global__ void ln_k(const float* __restrict__ x, const float* __restrict__ g,
                     const float* __restrict__ b, float* __restrict__ out) {
    __shared__ float red[256];
    int row = blockIdx.x, tid = threadIdx.x;
    const float* xr = x + (size_t)row * E_;
    float s = 0.f;
    for (int e = tid; e < E_; e += 256) s += xr[e];
    red[tid] = s; __syncthreads();
    for (int k = 128; k > 0; k >>= 1) { if (tid < k) red[tid] += red[tid + k]; __syncthreads(); }
    float mean = red[0] * (1.f / E_); __syncthreads();
    float vs = 0.f;
    for (int e = tid; e < E_; e += 256) { float d = xr[e] - mean; vs += d * d; }
    red[tid] = vs; __syncthreads();
    for (int k = 128; k > 0; k >>= 1) { if (tid < k) red[tid] += red[tid + k]; __syncthreads(); }
    float inv = rsqrtf(red[0] * (1.f / E_) + EPS_);
    float* orow = out + (size_t)row * E_;
    for (int e = tid; e < E_; e += 256)
        orow[e] = (xr[e] - mean) * inv * g[e] + b[e];
}

// ---------------- pack Wq/Wk/Wv[l]: [H,E,HD] -> [E, H*HD] ----------------
__global__ void pack_k(const float* __restrict__ Wq, const float* __restrict__ Wk,
                       const float* __restrict__ Wv, int l,
                       float* __restrict__ wq, float* __restrict__ wk, float* __restrict__ wv) {
    int i = blockIdx.x * blockDim.x + threadIdx.x;
    if (i >= E_ * E_) return;
    int e = i >> 10;             // /E_
    int n = i & (E_ - 1);
    int h = n >> 6;              // /HD_
    int d = n & (HD_ - 1);
    size_t src = (((size_t)l * H_ + h) * E_ + e) * HD_ + d;
    wq[i] = Wq[src]; wk[i] = Wk[src]; wv[i] = Wv[src];
}

// ---------------- fp32 GEMM: C[M,N] = A[M,K]*B[K,N] (+bias)(+res)(relu) ----------------
// 128x128 tile, 256 threads, 8x8 per thread (split-tile), BK=8.
// Requires M%128==0, N%128==0, K%8==0 (all shapes here satisfy this).
template<bool BIAS, bool RES, bool RELU>
__global__ void __launch_bounds__(256)
gemm_k(const float* __restrict__ A, const float* __restrict__ Bm,
       const float* __restrict__ bias, const float* __restrict__ res,
       float* __restrict__ C, int M, int N, int K) {
    __shared__ float As[8][132];
    __shared__ float Bs[8][132];
    int tid = threadIdx.x;
    int tx = tid & 15, ty = tid >> 4;
    int n0 = blockIdx.x * 128, m0 = blockIdx.y * 128;

    float acc[8][8];
#pragma unroll
    for (int i = 0; i < 8; i++)
#pragma unroll
        for (int j = 0; j < 8; j++) acc[i][j] = 0.f;

    int a_m = tid >> 1, a_k = (tid & 1) * 4;
    int b_n = (tid & 31) * 4, b_k = tid >> 5;
    const float* Aptr = A  + (size_t)(m0 + a_m) * K + a_k;
    const float* Bptr = Bm + (size_t)b_k * N + n0 + b_n;

    for (int k0 = 0; k0 < K; k0 += 8) {
        float4 av = *(const float4*)(Aptr + k0);
        float4 bv = *(const float4*)(Bptr + (size_t)k0 * N);
        As[a_k + 0][a_m] = av.x;
        As[a_k + 1][a_m] = av.y;
        As[a_k + 2][a_m] = av.z;
        As[a_k + 3][a_m] = av.w;
        *(float4*)&Bs[b_k][b_n] = bv;
        __syncthreads();
#pragma unroll
        for (int kk = 0; kk < 8; kk++) {
            float4 a0 = *(const float4*)&As[kk][ty * 4];
            float4 a1 = *(const float4*)&As[kk][64 + ty * 4];
            float4 b0 = *(const float4*)&Bs[kk][tx * 4];
            float4 b1 = *(const float4*)&Bs[kk][64 + tx * 4];
            float a_[8] = {a0.x, a0.y, a0.z, a0.w, a1.x, a1.y, a1.z, a1.w};
            float b_[8] = {b0.x, b0.y, b0.z, b0.w, b1.x, b1.y, b1.z, b1.w};
#pragma unroll
            for (int i = 0; i < 8; i++)
#pragma unroll
                for (int j = 0; j < 8; j++)
                    acc[i][j] += a_[i] * b_[j];
        }
        __syncthreads();
    }

    int rI[8], cJ[8];
#pragma unroll
    for (int i = 0; i < 4; i++) {
        rI[i] = ty * 4 + i;  rI[i + 4] = 64 + ty * 4 + i;
        cJ[i] = tx * 4 + i;  cJ[i + 4] = 64 + tx * 4 + i;
    }
#pragma unroll
    for (int i = 0; i < 8; i++) {
        size_t rowb = (size_t)(m0 + rI[i]) * N + n0;
#pragma unroll
        for (int j = 0; j < 8; j++) {
            float c = acc[i][j];
            if (BIAS) c += bias[n0 + cJ[j]];
            if (RES)  c += res[rowb + cJ[j]];
            if (RELU) c = fmaxf(c, 0.f);
            C[rowb + cJ[j]] = c;
        }
    }
}

// ---------------- causal attention: one CTA per (b,h,t) query row ----------------
// q,k,v layout: [B,T,H,HD] (i.e. [B,T,E] with n = h*HD+d). out same layout.
__global__ void attn_k(const float* __restrict__ q, const float* __restrict__ k,
                       const float* __restrict__ v, float* __restrict__ out) {
    __shared__ float sc[T_];        // 8 KB
    __shared__ float qs[HD_];
    __shared__ float red[256];
    int t = blockIdx.x, h = blockIdx.y, b = blockIdx.z, tid = threadIdx.x;
    size_t qoff = ((size_t)(b * T_ + t) * H_ + h) * HD_;
    if (tid < HD_) qs[tid] = q[qoff + tid];
    __syncthreads();

    const float4* q4 = (const float4*)qs;
    float lmax = -1e30f;
    for (int s = tid; s <= t; s += 256) {
        const float4* k4 = (const float4*)(k + ((size_t)(b * T_ + s) * H_ + h) * HD_);
        float dot = 0.f;
#pragma unroll
        for (int i = 0; i < HD_ / 4; i++) {
            float4 a = q4[i], c = k4[i];
            dot += a.x * c.x + a.y * c.y + a.z * c.z + a.w * c.w;
        }
        dot *= 0.125f;               // HD^-0.5
        sc[s] = dot;
        lmax = fmaxf(lmax, dot);
    }
    red[tid] = lmax; __syncthreads();
    for (int s2 = 128; s2 > 0; s2 >>= 1) { if (tid < s2) red[tid] = fmaxf(red[tid], red[tid + s2]); __syncthreads(); }
    float mx = red[0]; __syncthreads();

    float lsum = 0.f;
    for (int s = tid; s <= t; s += 256) { float e = expf(sc[s] - mx); sc[s] = e; lsum += e; }
    red[tid] = lsum; __syncthreads();
    for (int s2 = 128; s2 > 0; s2 >>= 1) { if (tid < s2) red[tid] += red[tid + s2]; __syncthreads(); }
    float inv = 1.f / red[0]; __syncthreads();

    int g = tid >> 6, d = tid & 63;
    float acc = 0.f;
    for (int s = g; s <= t; s += 4)
        acc += sc[s] * v[((size_t)(b * T_ + s) * H_ + h) * HD_ + d];
    red[tid] = acc; __syncthreads();
    if (tid < 64) {
        float r = red[tid] + red[tid + 64] + red[tid + 128] + red[tid + 192];
        out[qoff + tid] = r * inv;
    }
}

// ---------------- per-row cross-entropy ----------------
__global__ void rowloss_k(const float* __restrict__ logits, const int* __restrict__ tgt,
                          float* __restrict__ rl) {
    __shared__ float red[256];
    int row = blockIdx.x, tid = threadIdx.x;
    const float* lr = logits + (size_t)row * V_;
    float lmax = -1e30f;
    for (int i = tid; i < V_; i += 256) lmax = fmaxf(lmax, lr[i]);
    red[tid] = lmax; __syncthreads();
    for (int k = 128; k > 0; k >>= 1) { if (tid < k) red[tid] = fmaxf(red[tid], red[tid + k]); __syncthreads(); }
    float mx = red[0]; __syncthreads();
    float s = 0.f;
    for (int i = tid; i < V_; i += 256) s += expf(lr[i] - mx);
    red[tid] = s; __syncthreads();
    for (int k = 128; k > 0; k >>= 1) { if (tid < k) red[tid] += red[tid + k]; __syncthreads(); }
    if (tid == 0) rl[row] = -(lr[tgt[row]] - mx - logf(red[0]));
}

__global__ void finloss_k(const float* __restrict__ rl, float* __restrict__ dst) {
    __shared__ float red[256];
    int tid = threadIdx.x;
    float s = 0.f;
    for (int i = tid; i < BT_; i += 256) s += rl[i];
    red[tid] = s; __syncthreads();
    for (int k = 128; k > 0; k >>= 1) { if (tid < k) red[tid] += red[tid + k]; __syncthreads(); }
    if (tid == 0) dst[0] = red[0] * (1.f / BT_);
}

// ---------------- launch ----------------
extern "C" void kernel_launch(void* const* d_in, const int* in_sizes, int n_in,
                              void* d_out, int out_size) {
    const int*   idx     = (const int*)  d_in[0];
    const int*   targets = (const int*)  d_in[1];
    const float* tok     = (const float*)d_in[2];
    const float* pos     = (const float*)d_in[3];
    const float* Wq      = (const float*)d_in[4];
    const float* Wk      = (const float*)d_in[5];
    const float* Wv      = (const float*)d_in[6];
    const float* Wproj   = (const float*)d_in[7];
    const float* bproj   = (const float*)d_in[8];
    const float* ln1g    = (const float*)d_in[9];
    const float* ln1b    = (const float*)d_in[10];
    const float* ln2g    = (const float*)d_in[11];
    const float* ln2b    = (const float*)d_in[12];
    const float* W1      = (const float*)d_in[13];
    const float* b1      = (const float*)d_in[14];
    const float* W2      = (const float*)d_in[15];
    const float* b2      = (const float*)d_in[16];
    const float* lnfg    = (const float*)d_in[17];
    const float* lnfb    = (const float*)d_in[18];
    const float* Whead   = (const float*)d_in[19];
    const float* bhead   = (const float*)d_in[20];

    float *x, *h, *q, *k, *v, *a, *ff, *wq, *wk, *wv, *lgs, *rl, *dummy;
    cudaGetSymbolAddress((void**)&x,  g_x);
    cudaGetSymbolAddress((void**)&h,  g_h);
    cudaGetSymbolAddress((void**)&q,  g_q);
    cudaGetSymbolAddress((void**)&k,  g_k);
    cudaGetSymbolAddress((void**)&v,  g_v);
    cudaGetSymbolAddress((void**)&a,  g_a);
    cudaGetSymbolAddress((void**)&ff, g_ff);
    cudaGetSymbolAddress((void**)&wq, g_wq);
    cudaGetSymbolAddress((void**)&wk, g_wk);
    cudaGetSymbolAddress((void**)&wv, g_wv);
    cudaGetSymbolAddress((void**)&lgs, g_logits);
    cudaGetSymbolAddress((void**)&rl, g_rowloss);
    cudaGetSymbolAddress((void**)&dummy, g_loss_dummy);

    float* out = (float*)d_out;
    const long long BTV = (long long)BT_ * V_;
    float* logits   = ((long long)out_size >= BTV) ? out : lgs;
    float* loss_dst = ((long long)out_size == BTV + 1) ? (out + BTV)
                    : (((long long)out_size < BTV) ? out : dummy);

    embed_k<<<(BT_ * E_ + 255) / 256, 256>>>(idx, tok, pos, x);

    for (int l = 0; l < L_; l++) {
        ln_k<<<BT_, 256>>>(x, ln1g + l * E_, ln1b + l * E_, h);
        pack_k<<<(E_ * E_ + 255) / 256, 256>>>(Wq, Wk, Wv, l, wq, wk, wv);

        dim3 gE(E_ / 128, BT_ / 128);
        gemm_k<false, false, false><<<gE, 256>>>(h, wq, nullptr, nullptr, q, BT_, E_, E_);
        gemm_k<false, false, false><<<gE, 256>>>(h, wk, nullptr, nullptr, k, BT_, E_, E_);
        gemm_k<false, false, false><<<gE, 256>>>(h, wv, nullptr, nullptr, v, BT_, E_, E_);

        attn_k<<<dim3(T_, H_, B_), 256>>>(q, k, v, a);

        gemm_k<true, true, false><<<gE, 256>>>(a, Wproj + (size_t)l * E_ * E_, bproj + l * E_,
                                               x, x, BT_, E_, E_);

        ln_k<<<BT_, 256>>>(x, ln2g + l * E_, ln2b + l * E_, h);

        gemm_k<true, false, true><<<dim3(F_ / 128, BT_ / 128), 256>>>(
            h, W1 + (size_t)l * E_ * F_, b1 + l * F_, nullptr, ff, BT_, F_, E_);

        gemm_k<true, true, false><<<gE, 256>>>(
            ff, W2 + (size_t)l * F_ * E_, b2 + l * E_, x, x, BT_, E_, F_);
    }

    ln_k<<<BT_, 256>>>(x, lnfg, lnfb, h);

    gemm_k<true, false, false><<<dim3(V_ / 128, BT_ / 128), 256>>>(
        h, Whead, bhead, nullptr, logits, BT_, V_, E_);

    rowloss_k<<<BT_, 256>>>(logits, targets, rl);
    finloss_k<<<1, 256>>>(rl, loss_dst);
}

// round 14
// speedup vs baseline: 3.4951x; 3.4951x over previous
#include <cuda_runtime.h>
#include <math.h>
#include <stdint.h>

#define B_   2
#define T_   2048
#define E_   1024
#define H_   16
#define HD_  64
#define L_   4
#define V_   32000
#define F_   4096
#define BT_  (B_*T_)
#define EPS_ 1e-5f

// ---------------- device scratch ----------------
__device__ float g_x [BT_*E_];
__device__ float g_h [BT_*E_];
__device__ float g_q [BT_*E_];
__device__ float g_k [BT_*E_];
__device__ float g_v [BT_*E_];
__device__ float g_a [BT_*E_];
__device__ float g_ff[(size_t)BT_*F_];
__device__ float g_wqT[E_*E_];
__device__ float g_wkT[E_*E_];
__device__ float g_wvT[E_*E_];
__device__ float g_wpT[E_*E_];
__device__ float g_w1T[(size_t)E_*F_];
__device__ float g_w2T[(size_t)E_*F_];
__device__ float g_whT[(size_t)V_*E_];
__device__ float g_logits[(size_t)BT_*V_];
__device__ float g_rowloss[BT_];
__device__ float g_loss_dummy[1];

// ---------------- helpers ----------------
__device__ __forceinline__ uint32_t smem_u32(const void* p) {
    uint32_t a;
    asm("{ .reg .u64 t; cvta.to.shared.u64 t, %1; cvt.u32.u64 %0, t; }" : "=r"(a) : "l"(p));
    return a;
}
__device__ __forceinline__ float rna(float x) {
    float r; asm("cvt.rna.tf32.f32 %0, %1;" : "=f"(r) : "f"(x)); return r;
}
#define CP_ASYNC16(saddr, gptr) \
    asm volatile("cp.async.cg.shared.global [%0], [%1], 16;" :: "r"(saddr), "l"(gptr))
#define CP_COMMIT() asm volatile("cp.async.commit_group;")
#define CP_WAIT1()  asm volatile("cp.async.wait_group 1;")
#define CP_WAIT0()  asm volatile("cp.async.wait_group 0;")

__device__ __forceinline__ void mma_tf32(float* d, const uint32_t* a, const uint32_t* b) {
    asm volatile("mma.sync.aligned.m16n8k8.row.col.f32.tf32.tf32.f32 "
        "{%0,%1,%2,%3}, {%4,%5,%6,%7}, {%8,%9}, {%0,%1,%2,%3};"
        : "+f"(d[0]), "+f"(d[1]), "+f"(d[2]), "+f"(d[3])
        : "r"(a[0]), "r"(a[1]), "r"(a[2]), "r"(a[3]), "r"(b[0]), "r"(b[1]));
}

// ---------------- embedding ----------------
__global__ void embed_k(const int* __restrict__ idx, const float* __restrict__ tok,
                        const float* __restrict__ pos, float* __restrict__ x) {
    int i = blockIdx.x * blockDim.x + threadIdx.x;
    if (i >= BT_ * E_) return;
    int e = i & (E_-1); int bt = i >> 10; int t = bt & (T_-1);
    x[i] = tok[(size_t)idx[bt]*E_ + e] + pos[(size_t)t*E_ + e];
}

// ---------------- layernorm (rna output: feeds GEMM A) ----------------
__global__ void ln_k(const float* __restrict__ x, const float* __restrict__ g,
                     const float* __restrict__ b, float* __restrict__ out) {
    __shared__ float red[256];
    int row = blockIdx.x, tid = threadIdx.x;
    const float* xr = x + (size_t)row * E_;
    float s = 0.f;
    for (int e = tid; e < E_; e += 256) s += xr[e];
    red[tid] = s; __syncthreads();
    for (int k = 128; k > 0; k >>= 1) { if (tid < k) red[tid] += red[tid+k]; __syncthreads(); }
    float mean = red[0] * (1.f/E_); __syncthreads();
    float vs = 0.f;
    for (int e = tid; e < E_; e += 256) { float d = xr[e]-mean; vs += d*d; }
    red[tid] = vs; __syncthreads();
    for (int k = 128; k > 0; k >>= 1) { if (tid < k) red[tid] += red[tid+k]; __syncthreads(); }
    float inv = rsqrtf(red[0]*(1.f/E_) + EPS_);
    float* orow = out + (size_t)row * E_;
    for (int e = tid; e < E_; e += 256)
        orow[e] = rna((xr[e]-mean)*inv*g[e] + b[e]);
}

// ---------------- transpose+rna: in[R,C] -> out[C,R], z-batched ----------------
__global__ void transpose_k(const float* __restrict__ in, float* __restrict__ out,
                            int R, int C, long in_zs, long out_zs) {
    __shared__ float tile[32][33];
    const float* inz = in + (size_t)blockIdx.z * in_zs;
    float* outz = out + (size_t)blockIdx.z * out_zs;
    int c0 = blockIdx.x * 32, r0 = blockIdx.y * 32;
    int tx = threadIdx.x, ty = threadIdx.y;
    for (int i = ty; i < 32; i += 8)
        tile[i][tx] = inz[(size_t)(r0+i)*C + c0 + tx];
    __syncthreads();
    for (int i = ty; i < 32; i += 8)
        outz[(size_t)(c0+i)*R + r0 + tx] = rna(tile[tx][i]);
}

// ---------------- tf32 mma.sync GEMM: C[M,N] = A[M,K] @ Bt[N,K]^T ----------------
// 128x128 CTA tile, BK=32, 256 threads (8 warps, warp tile 64x32),
// double-buffered smem via cp.async. Requires M%128==0, N%128==0, K%32==0.
#define SM_STRIDE 36
#define GEMM_SMEM (4*128*SM_STRIDE*4)   // As[2]+Bs[2] = 73728 bytes
template<bool BIAS, bool RES, bool RELU, bool RNAO>
__global__ void __launch_bounds__(256)
gemm_mma(const float* __restrict__ A, const float* __restrict__ Bt,
         const float* __restrict__ bias, const float* __restrict__ res,
         float* __restrict__ C, int M, int N, int K) {
    extern __shared__ float smf[];
    float* As = smf;                       // [2][128][36]
    float* Bs = smf + 2*128*SM_STRIDE;     // [2][128][36]
    const int tid = threadIdx.x;
    const int wid = tid >> 5, lane = tid & 31;
    const int lr = lane >> 2, lc = lane & 3;
    const int warp_m = wid & 1, warp_n = wid >> 1;
    const int m0 = blockIdx.y * 128, n0 = blockIdx.x * 128;

    // global->smem load mapping: each thread owns one row, 16 consecutive floats
    const int lrow = tid >> 1, lcol = (tid & 1) * 16;
    const float* Ag = A  + (size_t)(m0 + lrow) * K + lcol;
    const float* Bg = Bt + (size_t)(n0 + lrow) * K + lcol;
    const uint32_t sA = smem_u32(As) + (uint32_t)(lrow * SM_STRIDE + lcol) * 4u;
    const uint32_t sB = smem_u32(Bs) + (uint32_t)(lrow * SM_STRIDE + lcol) * 4u;
    const uint32_t bufstep = 128u * SM_STRIDE * 4u;

    float acc[4][4][4];
#pragma unroll
    for (int i = 0; i < 4; i++)
#pragma unroll
        for (int j = 0; j < 4; j++)
#pragma unroll
            for (int r = 0; r < 4; r++) acc[i][j][r] = 0.f;

    const int nk = K >> 5;

    // preload tile 0
    {
        const float* ap = Ag; const float* bp = Bg;
#pragma unroll
        for (int j = 0; j < 4; j++) {
            CP_ASYNC16(sA + j*16u, ap + j*4);
            CP_ASYNC16(sB + j*16u, bp + j*4);
        }
        CP_COMMIT();
    }

    for (int it = 0; it < nk; it++) {
        int buf = it & 1;
        if (it + 1 < nk) {
            int nb = (it + 1) & 1;
            const float* ap = Ag + (it + 1) * 32;
            const float* bp = Bg + (it + 1) * 32;
#pragma unroll
            for (int j = 0; j < 4; j++) {
                CP_ASYNC16(sA + nb*bufstep + j*16u, ap + j*4);
                CP_ASYNC16(sB + nb*bufstep + j*16u, bp + j*4);
            }
            CP_COMMIT();
            CP_WAIT1();
        } else {
            CP_WAIT0();
        }
        __syncthreads();

        const uint32_t* Ab = (const uint32_t*)(As + buf*128*SM_STRIDE + (warp_m*64)*SM_STRIDE);
        const uint32_t* Bb = (const uint32_t*)(Bs + buf*128*SM_STRIDE + (warp_n*32)*SM_STRIDE);
#pragma unroll
        for (int kk = 0; kk < 4; kk++) {
            int k0 = kk * 8;
            uint32_t afr[4][4], bfr[4][2];
#pragma unroll
            for (int mt = 0; mt < 4; mt++) {
                int r = mt*16 + lr;
                afr[mt][0] = Ab[(size_t)r      * SM_STRIDE + k0 + lc];
                afr[mt][1] = Ab[(size_t)(r+8)  * SM_STRIDE + k0 + lc];
                afr[mt][2] = Ab[(size_t)r      * SM_STRIDE + k0 + lc + 4];
                afr[mt][3] = Ab[(size_t)(r+8)  * SM_STRIDE + k0 + lc + 4];
            }
#pragma unroll
            for (int nt = 0; nt < 4; nt++) {
                int n = nt*8 + lr;
                bfr[nt][0] = Bb[(size_t)n * SM_STRIDE + k0 + lc];
                bfr[nt][1] = Bb[(size_t)n * SM_STRIDE + k0 + lc + 4];
            }
#pragma unroll
            for (int mt = 0; mt < 4; mt++)
#pragma unroll
                for (int nt = 0; nt < 4; nt++)
                    mma_tf32(acc[mt][nt], afr[mt], bfr[nt]);
        }
        __syncthreads();
    }

    // epilogue
#pragma unroll
    for (int mt = 0; mt < 4; mt++) {
        int r0 = m0 + warp_m*64 + mt*16 + lr;
#pragma unroll
        for (int nt = 0; nt < 4; nt++) {
            int col = n0 + warp_n*32 + nt*8 + lc*2;
            float b0 = 0.f, b1 = 0.f;
            if (BIAS) { b0 = bias[col]; b1 = bias[col+1]; }
#pragma unroll
            for (int half = 0; half < 2; half++) {
                int r = r0 + half*8;
                float c0 = acc[mt][nt][half*2+0] + b0;
                float c1 = acc[mt][nt][half*2+1] + b1;
                float* cp = C + (size_t)r * N + col;
                if (RES) {
                    const float* rp = res + (size_t)r * N + col;
                    c0 += rp[0]; c1 += rp[1];
                }
                if (RELU) { c0 = fmaxf(c0, 0.f); c1 = fmaxf(c1, 0.f); }
                if (RNAO) { c0 = rna(c0); c1 = rna(c1); }
                *(float2*)cp = make_float2(c0, c1);
            }
        }
    }
}

// ---------------- flash-tiled causal attention (64-query tile) ----------------
#define ATTN_SMEM 53504
__global__ void __launch_bounds__(256)
attn_flash(const float* __restrict__ q, const float* __restrict__ k,
           const float* __restrict__ v, float* __restrict__ o) {
    extern __shared__ float sm[];
    float* Ks = sm;                 // [64][68]
    float* Vs = sm + 64*68;         // [64][68]
    float* Ss = sm + 2*64*68;       // [64][65]
    float* redm = Ss + 64*65;       // [4][64]
    float* redl = redm + 256;       // [4][64]
    int tid = threadIdx.x;
    int i = tid & 63, jg = tid >> 6;
    int qt = blockIdx.x, h = blockIdx.y, b = blockIdx.z;
    size_t base_b = (size_t)b * T_ * E_ + h * 64;

    { // stage Q through Ks
        int j = tid >> 2, seg = tid & 3;
        const float4* qr = (const float4*)(q + base_b + (size_t)(qt*64 + j) * E_);
        float4* dst = (float4*)(Ks + j*68);
#pragma unroll
        for (int t4 = 0; t4 < 4; t4++) dst[seg*4 + t4] = qr[seg*4 + t4];
    }
    __syncthreads();
    float qreg[64];
    {
        const float4* src = (const float4*)(Ks + i*68);
#pragma unroll
        for (int d4 = 0; d4 < 16; d4++) {
            float4 t4 = src[d4];
            qreg[d4*4+0] = t4.x*0.125f; qreg[d4*4+1] = t4.y*0.125f;
            qreg[d4*4+2] = t4.z*0.125f; qreg[d4*4+3] = t4.w*0.125f;
        }
    }
    __syncthreads();

    float acc[16];
#pragma unroll
    for (int d = 0; d < 16; d++) acc[d] = 0.f;
    float mi = -1e30f, li = 0.f;

    for (int st = 0; st <= qt; st++) {
        {
            int j = tid >> 2, seg = tid & 3;
            size_t rb = base_b + (size_t)(st*64 + j) * E_;
            const float4* kr = (const float4*)(k + rb);
            const float4* vr = (const float4*)(v + rb);
            float4* kd = (float4*)(Ks + j*68);
            float4* vd = (float4*)(Vs + j*68);
#pragma unroll
            for (int t4 = 0; t4 < 4; t4++) { kd[seg*4+t4] = kr[seg*4+t4]; vd[seg*4+t4] = vr[seg*4+t4]; }
        }
        __syncthreads();

        float sreg[16];
        float lm = -1e30f;
        bool diag = (st == qt);
#pragma unroll
        for (int jj = 0; jj < 16; jj++) {
            int j = jg*16 + jj;
            const float4* kr = (const float4*)(Ks + j*68);
            float s = 0.f;
#pragma unroll
            for (int d4 = 0; d4 < 16; d4++) {
                float4 kv = kr[d4];
                s += qreg[d4*4+0]*kv.x + qreg[d4*4+1]*kv.y + qreg[d4*4+2]*kv.z + qreg[d4*4+3]*kv.w;
            }
            if (diag && j > i) s = -1e30f;
            sreg[jj] = s;
            lm = fmaxf(lm, s);
        }
        redm[jg*64 + i] = lm;
        __syncthreads();
        float mt = fmaxf(fmaxf(redm[i], redm[64+i]), fmaxf(redm[128+i], redm[192+i]));
        float mnew = fmaxf(mi, mt);
        float corr = __expf(mi - mnew);
        float ls = 0.f;
#pragma unroll
        for (int jj = 0; jj < 16; jj++) {
            float p = __expf(sreg[jj] - mnew);
            Ss[i*65 + jg*16 + jj] = p;
            ls += p;
        }
        redl[jg*64 + i] = ls;
        __syncthreads();
        li = li*corr + redl[i] + redl[64+i] + redl[128+i] + redl[192+i];
        mi = mnew;
#pragma unroll
        for (int d = 0; d < 16; d++) acc[d] *= corr;
        int dbase = jg*16;
        for (int j = 0; j < 64; j++) {
            float p = Ss[i*65 + j];
            const float4* vrow = (const float4*)(Vs + j*68 + dbase);
#pragma unroll
            for (int d4 = 0; d4 < 4; d4++) {
                float4 vv = vrow[d4];
                acc[d4*4+0] += p*vv.x; acc[d4*4+1] += p*vv.y;
                acc[d4*4+2] += p*vv.z; acc[d4*4+3] += p*vv.w;
            }
        }
        __syncthreads();
    }
    float inv = 1.f / li;
    float* orow = o + base_b + (size_t)(qt*64 + i) * E_ + jg*16;
#pragma unroll
    for (int d4 = 0; d4 < 4; d4++) {
        float4 ov;
        ov.x = rna(acc[d4*4+0]*inv); ov.y = rna(acc[d4*4+1]*inv);
        ov.z = rna(acc[d4*4+2]*inv); ov.w = rna(acc[d4*4+3]*inv);
        *(float4*)(orow + d4*4) = ov;
    }
}

// ---------------- cross-entropy ----------------
__global__ void rowloss_k(const float* __restrict__ logits, const int* __restrict__ tgt,
                          float* __restrict__ rl) {
    __shared__ float red[256];
    int row = blockIdx.x, tid = threadIdx.x;
    const float* lr = logits + (size_t)row * V_;
    float lmax = -1e30f;
    for (int i = tid; i < V_; i += 256) lmax = fmaxf(lmax, lr[i]);
    red[tid] = lmax; __syncthreads();
    for (int k = 128; k > 0; k >>= 1) { if (tid < k) red[tid] = fmaxf(red[tid], red[tid+k]); __syncthreads(); }
    float mx = red[0]; __syncthreads();
    float s = 0.f;
    for (int i = tid; i < V_; i += 256) s += expf(lr[i] - mx);
    red[tid] = s; __syncthreads();
    for (int k = 128; k > 0; k >>= 1) { if (tid < k) red[tid] += red[tid+k]; __syncthreads(); }
    if (tid == 0) rl[row] = -(lr[tgt[row]] - mx - logf(red[0]));
}
__global__ void finloss_k(const float* __restrict__ rl, float* __restrict__ dst) {
    __shared__ float red[256];
    int tid = threadIdx.x;
    float s = 0.f;
    for (int i = tid; i < BT_; i += 256) s += rl[i];
    red[tid] = s; __syncthreads();
    for (int k = 128; k > 0; k >>= 1) { if (tid < k) red[tid] += red[tid+k]; __syncthreads(); }
    if (tid == 0) dst[0] = red[0] * (1.f/BT_);
}

// ---------------- launch ----------------
extern "C" void kernel_launch(void* const* d_in, const int* in_sizes, int n_in,
                              void* d_out, int out_size) {
    const int*   idx     = (const int*)  d_in[0];
    const int*   targets = (const int*)  d_in[1];
    const float* tok     = (const float*)d_in[2];
    const float* pos     = (const float*)d_in[3];
    const float* Wq      = (const float*)d_in[4];
    const float* Wk      = (const float*)d_in[5];
    const float* Wv      = (const float*)d_in[6];
    const float* Wproj   = (const float*)d_in[7];
    const float* bproj   = (const float*)d_in[8];
    const float* ln1g    = (const float*)d_in[9];
    const float* ln1b    = (const float*)d_in[10];
    const float* ln2g    = (const float*)d_in[11];
    const float* ln2b    = (const float*)d_in[12];
    const float* W1      = (const float*)d_in[13];
    const float* b1      = (const float*)d_in[14];
    const float* W2      = (const float*)d_in[15];
    const float* b2      = (const float*)d_in[16];
    const float* lnfg    = (const float*)d_in[17];
    const float* lnfb    = (const float*)d_in[18];
    const float* Whead   = (const float*)d_in[19];
    const float* bhead   = (const float*)d_in[20];

    float *x,*h,*q,*k,*v,*a,*ff,*wqT,*wkT,*wvT,*wpT,*w1T,*w2T,*whT,*lgs,*rl,*dummy;
    cudaGetSymbolAddress((void**)&x, g_x);   cudaGetSymbolAddress((void**)&h, g_h);
    cudaGetSymbolAddress((void**)&q, g_q);   cudaGetSymbolAddress((void**)&k, g_k);
    cudaGetSymbolAddress((void**)&v, g_v);   cudaGetSymbolAddress((void**)&a, g_a);
    cudaGetSymbolAddress((void**)&ff, g_ff);
    cudaGetSymbolAddress((void**)&wqT, g_wqT); cudaGetSymbolAddress((void**)&wkT, g_wkT);
    cudaGetSymbolAddress((void**)&wvT, g_wvT); cudaGetSymbolAddress((void**)&wpT, g_wpT);
    cudaGetSymbolAddress((void**)&w1T, g_w1T); cudaGetSymbolAddress((void**)&w2T, g_w2T);
    cudaGetSymbolAddress((void**)&whT, g_whT);
    cudaGetSymbolAddress((void**)&lgs, g_logits);
    cudaGetSymbolAddress((void**)&rl, g_rowloss);
    cudaGetSymbolAddress((void**)&dummy, g_loss_dummy);

    cudaFuncSetAttribute(gemm_mma<false,false,false,false>, cudaFuncAttributeMaxDynamicSharedMemorySize, GEMM_SMEM);
    cudaFuncSetAttribute(gemm_mma<true,true,false,false>,  cudaFuncAttributeMaxDynamicSharedMemorySize, GEMM_SMEM);
    cudaFuncSetAttribute(gemm_mma<true,false,true,true>,   cudaFuncAttributeMaxDynamicSharedMemorySize, GEMM_SMEM);
    cudaFuncSetAttribute(gemm_mma<true,false,false,false>, cudaFuncAttributeMaxDynamicSharedMemorySize, GEMM_SMEM);
    cudaFuncSetAttribute(attn_flash, cudaFuncAttributeMaxDynamicSharedMemorySize, ATTN_SMEM);

    float* out = (float*)d_out;
    const long long BTV = (long long)BT_ * V_;
    float* logits   = ((long long)out_size >= BTV) ? out : lgs;
    float* loss_dst = ((long long)out_size == BTV + 1) ? (out + BTV)
                    : (((long long)out_size < BTV) ? out : dummy);

    dim3 tb(32, 8);
    embed_k<<<(BT_*E_ + 255)/256, 256>>>(idx, tok, pos, x);

    dim3 gE(E_/128, BT_/128);
    for (int l = 0; l < L_; l++) {
        ln_k<<<BT_, 256>>>(x, ln1g + l*E_, ln1b + l*E_, h);

        // Wq/Wk/Wv[l]: [H,E,HD] -> per-head transpose -> [H*HD, E]
        transpose_k<<<dim3(HD_/32, E_/32, H_), tb>>>(Wq + (size_t)l*H_*E_*HD_, wqT, E_, HD_, (long)E_*HD_, (long)HD_*E_);
        transpose_k<<<dim3(HD_/32, E_/32, H_), tb>>>(Wk + (size_t)l*H_*E_*HD_, wkT, E_, HD_, (long)E_*HD_, (long)HD_*E_);
        transpose_k<<<dim3(HD_/32, E_/32, H_), tb>>>(Wv + (size_t)l*H_*E_*HD_, wvT, E_, HD_, (long)E_*HD_, (long)HD_*E_);

        gemm_mma<false,false,false,false><<<gE, 256, GEMM_SMEM>>>(h, wqT, 0, 0, q, BT_, E_, E_);
        gemm_mma<false,false,false,false><<<gE, 256, GEMM_SMEM>>>(h, wkT, 0, 0, k, BT_, E_, E_);
        gemm_mma<false,false,false,false><<<gE, 256, GEMM_SMEM>>>(h, wvT, 0, 0, v, BT_, E_, E_);

        attn_flash<<<dim3(T_/64, H_, B_), 256, ATTN_SMEM>>>(q, k, v, a);

        transpose_k<<<dim3(E_/32, E_/32, 1), tb>>>(Wproj + (size_t)l*E_*E_, wpT, E_, E_, 0, 0);
        gemm_mma<true,true,false,false><<<gE, 256, GEMM_SMEM>>>(a, wpT, bproj + l*E_, x, x, BT_, E_, E_);

        ln_k<<<BT_, 256>>>(x, ln2g + l*E_, ln2b + l*E_, h);

        transpose_k<<<dim3(F_/32, E_/32, 1), tb>>>(W1 + (size_t)l*E_*F_, w1T, E_, F_, 0, 0);
        gemm_mma<true,false,true,true><<<dim3(F_/128, BT_/128), 256, GEMM_SMEM>>>(h, w1T, b1 + l*F_, 0, ff, BT_, F_, E_);

        transpose_k<<<dim3(E_/32, F_/32, 1), tb>>>(W2 + (size_t)l*F_*E_, w2T, F_, E_, 0, 0);
        gemm_mma<true,true,false,false><<<gE, 256, GEMM_SMEM>>>(ff, w2T, b2 + l*E_, x, x, BT_, E_, F_);
    }

    ln_k<<<BT_, 256>>>(x, lnfg, lnfb, h);

    transpose_k<<<dim3(V_/32, E_/32, 1), tb>>>(Whead, whT, E_, V_, 0, 0);
    gemm_mma<true,false,false,false><<<dim3(V_/128, BT_/128), 256, GEMM_SMEM>>>(h, whT, bhead, 0, logits, BT_, V_, E_);

    rowloss_k<<<BT_, 256>>>(logits, targets, rl);
    finloss_k<<<1, 256>>>(rl, loss_dst);
}

// round 15
// speedup vs baseline: 3.7292x; 1.0670x over previous
#include <cuda_runtime.h>
#include <math.h>
#include <stdint.h>

#define B_   2
#define T_   2048
#define E_   1024
#define H_   16
#define HD_  64
#define L_   4
#define V_   32000
#define F_   4096
#define BT_  (B_*T_)
#define QS_  (3*E_)
#define EPS_ 1e-5f

// ---------------- device scratch ----------------
__device__ float g_x  [BT_*E_];
__device__ float g_h  [BT_*E_];
__device__ float g_a  [BT_*E_];
__device__ float g_qkv[(size_t)BT_*QS_];
__device__ float g_ff [(size_t)BT_*F_];
__device__ float g_wqkv[(size_t)E_*QS_];
__device__ float g_logits[(size_t)BT_*V_];
__device__ float g_rowloss[BT_];
__device__ float g_loss_dummy[1];

// ---------------- helpers ----------------
__device__ __forceinline__ uint32_t smem_u32(const void* p) {
    uint32_t a;
    asm("{ .reg .u64 t; cvta.to.shared.u64 t, %1; cvt.u32.u64 %0, t; }" : "=r"(a) : "l"(p));
    return a;
}
__device__ __forceinline__ float rna(float x) {
    float r; asm("cvt.rna.tf32.f32 %0, %1;" : "=f"(r) : "f"(x)); return r;
}
__device__ __forceinline__ uint32_t rna_u(uint32_t x) {
    uint32_t r; asm("cvt.rna.tf32.f32 %0, %1;" : "=r"(r) : "r"(x)); return r;
}
#define CP_ASYNC16(saddr, gptr) \
    asm volatile("cp.async.cg.shared.global [%0], [%1], 16;" :: "r"(saddr), "l"(gptr))
#define CP_COMMIT() asm volatile("cp.async.commit_group;")
#define CP_WAIT0()  asm volatile("cp.async.wait_group 0;")

__device__ __forceinline__ void mma_tf32(float* d, const uint32_t* a, const uint32_t* b) {
    asm volatile("mma.sync.aligned.m16n8k8.row.col.f32.tf32.tf32.f32 "
        "{%0,%1,%2,%3}, {%4,%5,%6,%7}, {%8,%9}, {%0,%1,%2,%3};"
        : "+f"(d[0]), "+f"(d[1]), "+f"(d[2]), "+f"(d[3])
        : "r"(a[0]), "r"(a[1]), "r"(a[2]), "r"(a[3]), "r"(b[0]), "r"(b[1]));
}

// ---------------- embedding ----------------
__global__ void embed_k(const int* __restrict__ idx, const float* __restrict__ tok,
                        const float* __restrict__ pos, float* __restrict__ x) {
    int i = blockIdx.x * blockDim.x + threadIdx.x;
    if (i >= BT_ * E_) return;
    int e = i & (E_-1); int bt = i >> 10; int t = bt & (T_-1);
    x[i] = tok[(size_t)idx[bt]*E_ + e] + pos[(size_t)t*E_ + e];
}

// ---------------- layernorm (rna output: feeds GEMM A) ----------------
__global__ void ln_k(const float* __restrict__ x, const float* __restrict__ g,
                     const float* __restrict__ b, float* __restrict__ out) {
    __shared__ float red[256];
    int row = blockIdx.x, tid = threadIdx.x;
    const float* xr = x + (size_t)row * E_;
    float s = 0.f;
    for (int e = tid; e < E_; e += 256) s += xr[e];
    red[tid] = s; __syncthreads();
    for (int k = 128; k > 0; k >>= 1) { if (tid < k) red[tid] += red[tid+k]; __syncthreads(); }
    float mean = red[0] * (1.f/E_); __syncthreads();
    float vs = 0.f;
    for (int e = tid; e < E_; e += 256) { float d = xr[e]-mean; vs += d*d; }
    red[tid] = vs; __syncthreads();
    for (int k = 128; k > 0; k >>= 1) { if (tid < k) red[tid] += red[tid+k]; __syncthreads(); }
    float inv = rsqrtf(red[0]*(1.f/E_) + EPS_);
    float* orow = out + (size_t)row * E_;
    for (int e = tid; e < E_; e += 256)
        orow[e] = rna((xr[e]-mean)*inv*g[e] + b[e]);
}

// ---------------- pack QKV weights: [H,E,HD]x3 -> [E, 3*E] row-major (+rna) ----------------
__global__ void pack_qkv(const float* __restrict__ Wq, const float* __restrict__ Wk,
                         const float* __restrict__ Wv, int l, float* __restrict__ out) {
    int i = blockIdx.x * blockDim.x + threadIdx.x;
    if (i >= E_ * E_) return;
    int e = i >> 10, n = i & (E_-1);
    int h = n >> 6, d = n & (HD_-1);
    size_t src = (((size_t)l * H_ + h) * E_ + e) * HD_ + d;
    size_t o = (size_t)e * QS_ + n;
    out[o]          = rna(Wq[src]);
    out[o + E_]     = rna(Wk[src]);
    out[o + 2*E_]   = rna(Wv[src]);
}

// ---------------- tf32 mma.sync GEMM: C[M,N] = A[M,K] @ B[K,N] ----------------
// A row-major (pre-rounded tf32), B row-major [K,N] (rounded in-kernel).
// 128x128 CTA tile, BK=32, 256 threads (8 warps, 64x32 warp tiles),
// cp.async double-buffer, single __syncthreads per K-iter, 2 CTAs/SM.
#define ASTR 36
#define BSTR 132
#define ASTEP (128*ASTR*4)
#define BSTEP (32*BSTR*4)
#define GEMM_SMEM (2*ASTEP + 2*BSTEP)   // 70656 B
template<bool BIAS, bool RES, bool RELU, bool RNAO>
__global__ void __launch_bounds__(256, 2)
gemm_mma(const float* __restrict__ A, const float* __restrict__ Bm,
         const float* __restrict__ bias, const float* __restrict__ res,
         float* __restrict__ C, int M, int N, int K) {
    extern __shared__ float smf[];
    float* As = smf;                    // [2][128][36]
    float* Bs = smf + 2*128*ASTR;       // [2][32][132]
    const int tid = threadIdx.x;
    const int wid = tid >> 5, lane = tid & 31;
    const int lr = lane >> 2, lc = lane & 3;
    const int warp_m = wid & 1, warp_n = wid >> 1;
    const int m0 = blockIdx.y * 128, n0 = blockIdx.x * 128;

    // A loads: thread -> (row=tid>>1, 16 floats at (tid&1)*16)
    const int arow = tid >> 1, acol = (tid & 1) * 16;
    const float* Ag = A + (size_t)(m0 + arow) * K + acol;
    const uint32_t sA = smem_u32(As) + (uint32_t)(arow * ASTR + acol) * 4u;
    // B loads: thread -> (k=tid>>3, 16 floats at (tid&7)*16)
    const int brow = tid >> 3, bcol = (tid & 7) * 16;
    const float* Bg = Bm + (size_t)brow * N + n0 + bcol;
    const uint32_t sB = smem_u32(Bs) + (uint32_t)(brow * BSTR + bcol) * 4u;

    float acc[4][4][4];
#pragma unroll
    for (int i = 0; i < 4; i++)
#pragma unroll
        for (int j = 0; j < 4; j++)
#pragma unroll
            for (int r = 0; r < 4; r++) acc[i][j][r] = 0.f;

    const int nk = K >> 5;

    // prologue: tile 0 -> buf 0
#pragma unroll
    for (int j = 0; j < 4; j++) {
        CP_ASYNC16(sA + j*16u, Ag + j*4);
        CP_ASYNC16(sB + j*16u, Bg + j*4);
    }
    CP_COMMIT();

    for (int it = 0; it < nk; it++) {
        const int buf = it & 1;
        CP_WAIT0();
        __syncthreads();
        if (it + 1 < nk) {
            const int nb = (it + 1) & 1;
            const float* ap = Ag + (it + 1) * 32;
            const float* bp = Bg + (size_t)((it + 1) * 32) * N;
#pragma unroll
            for (int j = 0; j < 4; j++) {
                CP_ASYNC16(sA + nb*ASTEP + j*16u, ap + j*4);
                CP_ASYNC16(sB + nb*BSTEP + j*16u, bp + j*4);
            }
            CP_COMMIT();
        }

        const uint32_t* Ab = (const uint32_t*)(As + buf*128*ASTR + (warp_m*64)*ASTR);
        const uint32_t* Bb = (const uint32_t*)(Bs + buf*32*BSTR) + warp_n*32;
#pragma unroll
        for (int kk = 0; kk < 4; kk++) {
            const int k0 = kk * 8;
            uint32_t afr[4][4], bfr[4][2];
#pragma unroll
            for (int mt = 0; mt < 4; mt++) {
                int r = mt*16 + lr;
                afr[mt][0] = Ab[(size_t)r     * ASTR + k0 + lc];
                afr[mt][1] = Ab[(size_t)(r+8) * ASTR + k0 + lc];
                afr[mt][2] = Ab[(size_t)r     * ASTR + k0 + lc + 4];
                afr[mt][3] = Ab[(size_t)(r+8) * ASTR + k0 + lc + 4];
            }
#pragma unroll
            for (int nt = 0; nt < 4; nt++) {
                bfr[nt][0] = rna_u(Bb[(size_t)(k0 + lc)     * BSTR + nt*8 + lr]);
                bfr[nt][1] = rna_u(Bb[(size_t)(k0 + lc + 4) * BSTR + nt*8 + lr]);
            }
#pragma unroll
            for (int mt = 0; mt < 4; mt++)
#pragma unroll
                for (int nt = 0; nt < 4; nt++)
                    mma_tf32(acc[mt][nt], afr[mt], bfr[nt]);
        }
    }

    // epilogue
#pragma unroll
    for (int mt = 0; mt < 4; mt++) {
        int r0 = m0 + warp_m*64 + mt*16 + lr;
#pragma unroll
        for (int nt = 0; nt < 4; nt++) {
            int col = n0 + warp_n*32 + nt*8 + lc*2;
            float b0 = 0.f, b1 = 0.f;
            if (BIAS) { b0 = bias[col]; b1 = bias[col+1]; }
#pragma unroll
            for (int half = 0; half < 2; half++) {
                int r = r0 + half*8;
                float c0 = acc[mt][nt][half*2+0] + b0;
                float c1 = acc[mt][nt][half*2+1] + b1;
                float* cp = C + (size_t)r * N + col;
                if (RES) {
                    const float* rp = res + (size_t)r * N + col;
                    c0 += rp[0]; c1 += rp[1];
                }
                if (RELU) { c0 = fmaxf(c0, 0.f); c1 = fmaxf(c1, 0.f); }
                if (RNAO) { c0 = rna(c0); c1 = rna(c1); }
                *(float2*)cp = make_float2(c0, c1);
            }
        }
    }
}

// ---------------- flash-tiled causal attention (64-query tile) ----------------
// q,k,v packed in qkv[BT, 3E]: q at +0, k at +E, v at +2E, head h at h*64.
#define ATTN_SMEM 53504
__global__ void __launch_bounds__(256)
attn_flash(const float* __restrict__ qkv, float* __restrict__ o) {
    extern __shared__ float sm[];
    float* Ks = sm;                 // [64][68]
    float* Vs = sm + 64*68;         // [64][68]
    float* Ss = sm + 2*64*68;       // [64][65]
    float* redm = Ss + 64*65;       // [4][64]
    float* redl = redm + 256;       // [4][64]
    int tid = threadIdx.x;
    int i = tid & 63, jg = tid >> 6;
    int qt = blockIdx.x, h = blockIdx.y, b = blockIdx.z;
    size_t rowb = (size_t)b * T_;
    size_t hoff = h * 64;

    { // stage Q through Ks
        int j = tid >> 2, seg = tid & 3;
        const float4* qr = (const float4*)(qkv + (rowb + qt*64 + j) * QS_ + hoff);
        float4* dst = (float4*)(Ks + j*68);
#pragma unroll
        for (int t4 = 0; t4 < 4; t4++) dst[seg*4 + t4] = qr[seg*4 + t4];
    }
    __syncthreads();
    float qreg[64];
    {
        const float4* src = (const float4*)(Ks + i*68);
#pragma unroll
        for (int d4 = 0; d4 < 16; d4++) {
            float4 t4 = src[d4];
            qreg[d4*4+0] = t4.x*0.125f; qreg[d4*4+1] = t4.y*0.125f;
            qreg[d4*4+2] = t4.z*0.125f; qreg[d4*4+3] = t4.w*0.125f;
        }
    }
    __syncthreads();

    float acc[16];
#pragma unroll
    for (int d = 0; d < 16; d++) acc[d] = 0.f;
    float mi = -1e30f, li = 0.f;

    for (int st = 0; st <= qt; st++) {
        {
            int j = tid >> 2, seg = tid & 3;
            size_t rb = (rowb + st*64 + j) * QS_ + hoff;
            const float4* kr = (const float4*)(qkv + rb + E_);
            const float4* vr = (const float4*)(qkv + rb + 2*E_);
            float4* kd = (float4*)(Ks + j*68);
            float4* vd = (float4*)(Vs + j*68);
#pragma unroll
            for (int t4 = 0; t4 < 4; t4++) { kd[seg*4+t4] = kr[seg*4+t4]; vd[seg*4+t4] = vr[seg*4+t4]; }
        }
        __syncthreads();

        float sreg[16];
        float lm = -1e30f;
        bool diag = (st == qt);
#pragma unroll
        for (int jj = 0; jj < 16; jj++) {
            int j = jg*16 + jj;
            const float4* kr = (const float4*)(Ks + j*68);
            float s = 0.f;
#pragma unroll
            for (int d4 = 0; d4 < 16; d4++) {
                float4 kv = kr[d4];
                s += qreg[d4*4+0]*kv.x + qreg[d4*4+1]*kv.y + qreg[d4*4+2]*kv.z + qreg[d4*4+3]*kv.w;
            }
            if (diag && j > i) s = -1e30f;
            sreg[jj] = s;
            lm = fmaxf(lm, s);
        }
        redm[jg*64 + i] = lm;
        __syncthreads();
        float mt = fmaxf(fmaxf(redm[i], redm[64+i]), fmaxf(redm[128+i], redm[192+i]));
        float mnew = fmaxf(mi, mt);
        float corr = __expf(mi - mnew);
        float ls = 0.f;
#pragma unroll
        for (int jj = 0; jj < 16; jj++) {
            float p = __expf(sreg[jj] - mnew);
            Ss[i*65 + jg*16 + jj] = p;
            ls += p;
        }
        redl[jg*64 + i] = ls;
        __syncthreads();
        li = li*corr + redl[i] + redl[64+i] + redl[128+i] + redl[192+i];
        mi = mnew;
#pragma unroll
        for (int d = 0; d < 16; d++) acc[d] *= corr;
        int dbase = jg*16;
        for (int j = 0; j < 64; j++) {
            float p = Ss[i*65 + j];
            const float4* vrow = (const float4*)(Vs + j*68 + dbase);
#pragma unroll
            for (int d4 = 0; d4 < 4; d4++) {
                float4 vv = vrow[d4];
                acc[d4*4+0] += p*vv.x; acc[d4*4+1] += p*vv.y;
                acc[d4*4+2] += p*vv.z; acc[d4*4+3] += p*vv.w;
            }
        }
        __syncthreads();
    }
    float inv = 1.f / li;
    float* orow = o + (rowb + qt*64 + i) * E_ + hoff + jg*16;
#pragma unroll
    for (int d4 = 0; d4 < 4; d4++) {
        float4 ov;
        ov.x = rna(acc[d4*4+0]*inv); ov.y = rna(acc[d4*4+1]*inv);
        ov.z = rna(acc[d4*4+2]*inv); ov.w = rna(acc[d4*4+3]*inv);
        *(float4*)(orow + d4*4) = ov;
    }
}

// ---------------- cross-entropy ----------------
__global__ void rowloss_k(const float* __restrict__ logits, const int* __restrict__ tgt,
                          float* __restrict__ rl) {
    __shared__ float red[256];
    int row = blockIdx.x, tid = threadIdx.x;
    const float* lr = logits + (size_t)row * V_;
    float lmax = -1e30f;
    for (int i = tid; i < V_; i += 256) lmax = fmaxf(lmax, lr[i]);
    red[tid] = lmax; __syncthreads();
    for (int k = 128; k > 0; k >>= 1) { if (tid < k) red[tid] = fmaxf(red[tid], red[tid+k]); __syncthreads(); }
    float mx = red[0]; __syncthreads();
    float s = 0.f;
    for (int i = tid; i < V_; i += 256) s += expf(lr[i] - mx);
    red[tid] = s; __syncthreads();
    for (int k = 128; k > 0; k >>= 1) { if (tid < k) red[tid] += red[tid+k]; __syncthreads(); }
    if (tid == 0) rl[row] = -(lr[tgt[row]] - mx - logf(red[0]));
}
__global__ void finloss_k(const float* __restrict__ rl, float* __restrict__ dst) {
    __shared__ float red[256];
    int tid = threadIdx.x;
    float s = 0.f;
    for (int i = tid; i < BT_; i += 256) s += rl[i];
    red[tid] = s; __syncthreads();
    for (int k = 128; k > 0; k >>= 1) { if (tid < k) red[tid] += red[tid+k]; __syncthreads(); }
    if (tid == 0) dst[0] = red[0] * (1.f/BT_);
}

// ---------------- launch ----------------
extern "C" void kernel_launch(void* const* d_in, const int* in_sizes, int n_in,
                              void* d_out, int out_size) {
    const int*   idx     = (const int*)  d_in[0];
    const int*   targets = (const int*)  d_in[1];
    const float* tok     = (const float*)d_in[2];
    const float* pos     = (const float*)d_in[3];
    const float* Wq      = (const float*)d_in[4];
    const float* Wk      = (const float*)d_in[5];
    const float* Wv      = (const float*)d_in[6];
    const float* Wproj   = (const float*)d_in[7];
    const float* bproj   = (const float*)d_in[8];
    const float* ln1g    = (const float*)d_in[9];
    const float* ln1b    = (const float*)d_in[10];
    const float* ln2g    = (const float*)d_in[11];
    const float* ln2b    = (const float*)d_in[12];
    const float* W1      = (const float*)d_in[13];
    const float* b1      = (const float*)d_in[14];
    const float* W2      = (const float*)d_in[15];
    const float* b2      = (const float*)d_in[16];
    const float* lnfg    = (const float*)d_in[17];
    const float* lnfb    = (const float*)d_in[18];
    const float* Whead   = (const float*)d_in[19];
    const float* bhead   = (const float*)d_in[20];

    float *x,*h,*a,*qkv,*ff,*wqkv,*lgs,*rl,*dummy;
    cudaGetSymbolAddress((void**)&x, g_x);     cudaGetSymbolAddress((void**)&h, g_h);
    cudaGetSymbolAddress((void**)&a, g_a);     cudaGetSymbolAddress((void**)&qkv, g_qkv);
    cudaGetSymbolAddress((void**)&ff, g_ff);   cudaGetSymbolAddress((void**)&wqkv, g_wqkv);
    cudaGetSymbolAddress((void**)&lgs, g_logits);
    cudaGetSymbolAddress((void**)&rl, g_rowloss);
    cudaGetSymbolAddress((void**)&dummy, g_loss_dummy);

    cudaFuncSetAttribute(gemm_mma<false,false,false,false>, cudaFuncAttributeMaxDynamicSharedMemorySize, GEMM_SMEM);
    cudaFuncSetAttribute(gemm_mma<true,true,false,false>,  cudaFuncAttributeMaxDynamicSharedMemorySize, GEMM_SMEM);
    cudaFuncSetAttribute(gemm_mma<true,false,true,true>,   cudaFuncAttributeMaxDynamicSharedMemorySize, GEMM_SMEM);
    cudaFuncSetAttribute(gemm_mma<true,false,false,false>, cudaFuncAttributeMaxDynamicSharedMemorySize, GEMM_SMEM);
    cudaFuncSetAttribute(attn_flash, cudaFuncAttributeMaxDynamicSharedMemorySize, ATTN_SMEM);

    float* out = (float*)d_out;
    const long long BTV = (long long)BT_ * V_;
    float* logits   = ((long long)out_size >= BTV) ? out : lgs;
    float* loss_dst = ((long long)out_size == BTV + 1) ? (out + BTV)
                    : (((long long)out_size < BTV) ? out : dummy);

    embed_k<<<(BT_*E_ + 255)/256, 256>>>(idx, tok, pos, x);

    dim3 gQKV(QS_/128, BT_/128);
    dim3 gE(E_/128, BT_/128);
    for (int l = 0; l < L_; l++) {
        ln_k<<<BT_, 256>>>(x, ln1g + l*E_, ln1b + l*E_, h);
        pack_qkv<<<(E_*E_ + 255)/256, 256>>>(Wq, Wk, Wv, l, wqkv);

        gemm_mma<false,false,false,false><<<gQKV, 256, GEMM_SMEM>>>(h, wqkv, 0, 0, qkv, BT_, QS_, E_);

        attn_flash<<<dim3(T_/64, H_, B_), 256, ATTN_SMEM>>>(qkv, a);

        gemm_mma<true,true,false,false><<<gE, 256, GEMM_SMEM>>>(
            a, Wproj + (size_t)l*E_*E_, bproj + l*E_, x, x, BT_, E_, E_);

        ln_k<<<BT_, 256>>>(x, ln2g + l*E_, ln2b + l*E_, h);

        gemm_mma<true,false,true,true><<<dim3(F_/128, BT_/128), 256, GEMM_SMEM>>>(
            h, W1 + (size_t)l*E_*F_, b1 + l*F_, 0, ff, BT_, F_, E_);

        gemm_mma<true,true,false,false><<<gE, 256, GEMM_SMEM>>>(
            ff, W2 + (size_t)l*F_*E_, b2 + l*E_, x, x, BT_, E_, F_);
    }

    ln_k<<<BT_, 256>>>(x, lnfg, lnfb, h);

    gemm_mma<true,false,false,false><<<dim3(V_/128, BT_/128), 256, GEMM_SMEM>>>(
        h, Whead, bhead, 0, logits, BT_, V_, E_);

    rowloss_k<<<BT_, 256>>>(logits, targets, rl);
    finloss_k<<<1, 256>>>(rl, loss_dst);
}